// round 3
// baseline (speedup 1.0000x reference)
#include <cuda_runtime.h>

// SpikingAttentionJAX — single fused persistent kernel, minimal critical path.
// LIF scan collapses to per-token occurrence counts (per-entry updates commute;
// final state of entry t depends only on count n_t and v0[t]).
//
// ONE launch, ONE grid barrier:
//   P1: histogram token_seq into g_count (all-zero on entry)
//   -- grid barrier --
//   P2: per vocab entry: read count (int4), ZERO it inline (restores invariant
//       for next graph replay), replay n_t LIF steps, write gains (0.6/1.0);
//       warp-local top-5 via shuffles, warp 0 merges 40 -> block top-5;
//       threadfence + done-counter: LAST block merges 640 candidates and
//       writes the 5 winners (1.5). Tie-break: lower index wins (JAX top_k),
//       encoded by packing (ordered_float(v) << 32) | (~index).

static constexpr float DECAY     = 0.7f;
static constexpr float THETA     = 1.0f;
static constexpr float GAIN_UP   = 1.5f;
static constexpr float GAIN_DOWN = 0.6f;
static constexpr int   KW   = 5;
static constexpr int   NB   = 128;           // co-resident blocks
static constexpr int   NT   = 256;
static constexpr int   NW   = NT / 32;       // 8 warps
static constexpr int   MAXV = 4 * NB * NT;   // 131072 >= vocab (128000)

__device__ __align__(16) int g_count[MAXV];          // zero-init; kept zero
__device__ unsigned long long g_cand[NB * KW];
__device__ unsigned           g_barcnt = 0;
__device__ volatile unsigned  g_bargen = 0;          // monotonic across replays
__device__ unsigned           g_done   = 0;          // monotonic across replays

__device__ __forceinline__ unsigned ordered_bits(float f) {
    unsigned u = __float_as_uint(f);
    return (u & 0x80000000u) ? ~u : (u | 0x80000000u);
}

__device__ __forceinline__ unsigned long long warp_max(unsigned long long m) {
    #pragma unroll
    for (int off = 16; off > 0; off >>= 1) {
        unsigned long long o = __shfl_xor_sync(0xffffffffu, m, off);
        if (o > m) m = o;
    }
    return m;   // all lanes hold the max (butterfly)
}

__device__ __forceinline__ void grid_barrier() {
    __threadfence();
    __syncthreads();
    if (threadIdx.x == 0) {
        unsigned gen = g_bargen;
        if (atomicAdd(&g_barcnt, 1) == (unsigned)NB - 1) {
            g_barcnt = 0;
            __threadfence();
            g_bargen = gen + 1;
        } else {
            while (g_bargen == gen) { }
        }
        __threadfence();
    }
    __syncthreads();
}

__global__ __launch_bounds__(NT, 1)
void fused_spiking(const int* __restrict__ tok, const float* __restrict__ v0,
                   float* __restrict__ out, int seq, int vocab) {
    const int tid  = threadIdx.x;
    const int lane = tid & 31;
    const int wid  = tid >> 5;
    const int g    = blockIdx.x * NT + tid;

    __shared__ unsigned long long sw[NW * KW];   // 40 warp candidates
    __shared__ unsigned s_last;

    // ---- P1: histogram (seq=8192 < 32768 threads: single iteration) ----
    for (int i = g; i < seq; i += NB * NT) {
        int t = tok[i];
        t = t < 0 ? 0 : (t >= vocab ? vocab - 1 : t);
        atomicAdd(&g_count[t], 1);
    }

    grid_barrier();

    // ---- P2: gains + inline count re-zero + packed top-5 keys ----
    unsigned long long keys[4];
    #pragma unroll
    for (int j = 0; j < 4; j++) keys[j] = 0ull;

    const int base = 4 * g;
    if (base + 3 < vocab) {
        int4 c4 = __ldcg(reinterpret_cast<const int4*>(g_count) + g);
        reinterpret_cast<int4*>(g_count)[g] = make_int4(0, 0, 0, 0);  // re-zero
        float4 v4 = __ldg(reinterpret_cast<const float4*>(v0) + g);
        int   cnt[4] = {c4.x, c4.y, c4.z, c4.w};
        float vv[4]  = {v4.x, v4.y, v4.z, v4.w};
        float gn[4];
        #pragma unroll
        for (int j = 0; j < 4; j++) {
            float v = vv[j];
            int   s = 0;
            for (int it = 0; it < cnt[j]; it++) {
                float vn = DECAY * v + 1.0f;
                if (vn >= THETA) { v = vn - THETA; s++; }
                else             { v = vn; }
            }
            gn[j] = (s > 0) ? GAIN_DOWN : 1.0f;
            keys[j] = ((unsigned long long)ordered_bits(v) << 32)
                    | (unsigned long long)(0xFFFFFFFFu - (unsigned)(base + j));
        }
        reinterpret_cast<float4*>(out)[g] = make_float4(gn[0], gn[1], gn[2], gn[3]);
    } else if (base < vocab) {
        #pragma unroll
        for (int j = 0; j < 4; j++) {
            int i = base + j;
            if (i < vocab) {
                int   cnt = __ldcg(&g_count[i]);
                g_count[i] = 0;
                float v = v0[i];
                int   s = 0;
                for (int it = 0; it < cnt; it++) {
                    float vn = DECAY * v + 1.0f;
                    if (vn >= THETA) { v = vn - THETA; s++; }
                    else             { v = vn; }
                }
                out[i] = (s > 0) ? GAIN_DOWN : 1.0f;
                keys[j] = ((unsigned long long)ordered_bits(v) << 32)
                        | (unsigned long long)(0xFFFFFFFFu - (unsigned)i);
            }
        }
    }

    // ---- warp-local top-5 (shuffles only, no syncs) ----
    #pragma unroll
    for (int r = 0; r < KW; r++) {
        unsigned long long m = keys[0];
        #pragma unroll
        for (int j = 1; j < 4; j++) if (keys[j] > m) m = keys[j];
        m = warp_max(m);
        if (lane == 0) sw[wid * KW + r] = m;
        #pragma unroll
        for (int j = 0; j < 4; j++) if (keys[j] == m) keys[j] = 0ull;  // unique keys
    }
    __syncthreads();

    // ---- warp 0 merges 40 warp-candidates -> block top-5 -> g_cand ----
    if (wid == 0) {
        unsigned long long k0 = sw[lane];
        unsigned long long k1 = (lane < NW * KW - 32) ? sw[32 + lane] : 0ull;
        #pragma unroll
        for (int r = 0; r < KW; r++) {
            unsigned long long m = (k0 > k1) ? k0 : k1;
            m = warp_max(m);
            if (lane == 0) g_cand[blockIdx.x * KW + r] = m;
            if (k0 == m) k0 = 0ull;
            if (k1 == m) k1 = 0ull;
        }
    }

    // ---- last-done block performs the final merge ----
    if (tid == 0) {
        __threadfence();                         // publish g_cand writes
        unsigned old = atomicAdd(&g_done, 1);
        s_last = (((old + 1) % (unsigned)NB) == 0u) ? 1u : 0u;
    }
    __syncthreads();
    if (!s_last) return;
    __threadfence();                             // order candidate reads

    // merge NB*KW = 640 candidates with 256 threads (<=3 each, static regs)
    unsigned long long k0 = __ldcg(&g_cand[tid]);
    unsigned long long k1 = __ldcg(&g_cand[tid + NT]);
    unsigned long long k2 = (tid + 2 * NT < NB * KW) ? __ldcg(&g_cand[tid + 2 * NT]) : 0ull;

    __syncthreads();                             // sw reuse
    #pragma unroll
    for (int r = 0; r < KW; r++) {
        unsigned long long m = k0;
        if (k1 > m) m = k1;
        if (k2 > m) m = k2;
        m = warp_max(m);
        if (lane == 0) sw[wid * KW + r] = m;
        if (k0 == m) k0 = 0ull;
        if (k1 == m) k1 = 0ull;
        if (k2 == m) k2 = 0ull;
    }
    __syncthreads();

    if (wid == 0) {
        unsigned long long a0 = sw[lane];
        unsigned long long a1 = (lane < NW * KW - 32) ? sw[32 + lane] : 0ull;
        #pragma unroll
        for (int r = 0; r < KW; r++) {
            unsigned long long m = (a0 > a1) ? a0 : a1;
            m = warp_max(m);
            if (lane == 0 && m != 0ull) {
                unsigned idx = 0xFFFFFFFFu - (unsigned)(m & 0xFFFFFFFFull);
                out[idx] = GAIN_UP;
            }
            if (a0 == m) a0 = 0ull;
            if (a1 == m) a1 = 0ull;
        }
    }
}

extern "C" void kernel_launch(void* const* d_in, const int* in_sizes, int n_in,
                              void* d_out, int out_size) {
    const int*   tok = (const int*)d_in[0];
    const float* v0  = (const float*)d_in[1];
    const int seq   = in_sizes[0];
    const int vocab = in_sizes[1];
    float* out = (float*)d_out;

    fused_spiking<<<NB, NT>>>(tok, v0, out, seq, vocab);
}

// round 4
// speedup vs baseline: 1.0175x; 1.0175x over previous
#include <cuda_runtime.h>

// SpikingAttentionJAX — two-kernel pipeline (kernel boundary = free grid sync).
// The sequential LIF scan collapses to per-token occurrence counts: updates to
// distinct vocab entries commute, and entry t's final state depends only on
// (count n_t, v0[t]).
//
//   K1: histogram token_seq into g_count (g_count all-zero on entry).
//   K2: per vocab entry (4/thread, vectorized): read count, re-zero inline
//       (restores invariant for the next graph replay), replay n_t LIF steps,
//       write gains (0.6 spiked / 1.0); warp-shuffle top-5 of v_final, warp 0
//       merges to block top-5 -> g_cand; done-counter: LAST block merges all
//       candidates and writes the 5 winners (1.5). Tie-break lower-index-wins
//       (JAX top_k) via key = (ordered_float(v) << 32) | ~index.

static constexpr float DECAY     = 0.7f;
static constexpr float THETA     = 1.0f;
static constexpr float GAIN_UP   = 1.5f;
static constexpr float GAIN_DOWN = 0.6f;
static constexpr int   KW   = 5;
static constexpr int   NT   = 256;
static constexpr int   NW   = NT / 32;
static constexpr int   MAXV = 131072;        // >= vocab (128000)
static constexpr int   MAXB = 256;           // >= K2 grid (125)

__device__ __align__(16) int g_count[MAXV];            // zero-init; kept zero
__device__ unsigned long long g_cand[MAXB * KW];
__device__ unsigned g_done = 0;                        // monotonic across replays

__device__ __forceinline__ unsigned ordered_bits(float f) {
    unsigned u = __float_as_uint(f);
    return (u & 0x80000000u) ? ~u : (u | 0x80000000u);
}

__device__ __forceinline__ unsigned long long warp_max(unsigned long long m) {
    #pragma unroll
    for (int off = 16; off > 0; off >>= 1) {
        unsigned long long o = __shfl_xor_sync(0xffffffffu, m, off);
        if (o > m) m = o;
    }
    return m;    // butterfly: all lanes hold the max
}

// ---------------------------------------------------------------- K1: histogram
__global__ void k_hist(const int* __restrict__ tok, int n, int vocab) {
    int i = blockIdx.x * blockDim.x + threadIdx.x;
    if (i < n) {
        int t = tok[i];
        t = t < 0 ? 0 : (t >= vocab ? vocab - 1 : t);
        atomicAdd(&g_count[t], 1);
    }
}

// ---------------------------------------------------------------- K2: gains + top-5
__global__ __launch_bounds__(NT, 1)
void k_gains(const float* __restrict__ v0, float* __restrict__ out,
             int vocab, int nblocks) {
    const int tid  = threadIdx.x;
    const int lane = tid & 31;
    const int wid  = tid >> 5;
    const int g    = blockIdx.x * NT + tid;

    __shared__ unsigned long long sw[NW * KW];
    __shared__ unsigned s_last;

    unsigned long long keys[4];
    #pragma unroll
    for (int j = 0; j < 4; j++) keys[j] = 0ull;

    const int base = 4 * g;
    if (base + 3 < vocab) {
        int4 c4 = __ldcg(reinterpret_cast<const int4*>(g_count) + g);
        reinterpret_cast<int4*>(g_count)[g] = make_int4(0, 0, 0, 0);  // re-zero
        float4 v4 = __ldg(reinterpret_cast<const float4*>(v0) + g);
        int   cnt[4] = {c4.x, c4.y, c4.z, c4.w};
        float vv[4]  = {v4.x, v4.y, v4.z, v4.w};
        float gn[4];
        #pragma unroll
        for (int j = 0; j < 4; j++) {
            float v = vv[j];
            int   s = 0;
            for (int it = 0; it < cnt[j]; it++) {
                float vn = DECAY * v + 1.0f;
                if (vn >= THETA) { v = vn - THETA; s++; }
                else             { v = vn; }
            }
            gn[j] = (s > 0) ? GAIN_DOWN : 1.0f;
            keys[j] = ((unsigned long long)ordered_bits(v) << 32)
                    | (unsigned long long)(0xFFFFFFFFu - (unsigned)(base + j));
        }
        reinterpret_cast<float4*>(out)[g] = make_float4(gn[0], gn[1], gn[2], gn[3]);
    } else if (base < vocab) {
        #pragma unroll
        for (int j = 0; j < 4; j++) {
            int i = base + j;
            if (i < vocab) {
                int   cnt = __ldcg(&g_count[i]);
                g_count[i] = 0;
                float v = v0[i];
                int   s = 0;
                for (int it = 0; it < cnt; it++) {
                    float vn = DECAY * v + 1.0f;
                    if (vn >= THETA) { v = vn - THETA; s++; }
                    else             { v = vn; }
                }
                out[i] = (s > 0) ? GAIN_DOWN : 1.0f;
                keys[j] = ((unsigned long long)ordered_bits(v) << 32)
                        | (unsigned long long)(0xFFFFFFFFu - (unsigned)i);
            }
        }
    }

    // warp-local top-5 (shuffles only)
    #pragma unroll
    for (int r = 0; r < KW; r++) {
        unsigned long long m = keys[0];
        #pragma unroll
        for (int j = 1; j < 4; j++) if (keys[j] > m) m = keys[j];
        m = warp_max(m);
        if (lane == 0) sw[wid * KW + r] = m;
        #pragma unroll
        for (int j = 0; j < 4; j++) if (keys[j] == m) keys[j] = 0ull;
    }
    __syncthreads();

    // warp 0: merge NW*KW = 40 warp candidates -> block top-5 -> g_cand
    if (wid == 0) {
        unsigned long long k0 = sw[lane];
        unsigned long long k1 = (lane < NW * KW - 32) ? sw[32 + lane] : 0ull;
        #pragma unroll
        for (int r = 0; r < KW; r++) {
            unsigned long long m = (k0 > k1) ? k0 : k1;
            m = warp_max(m);
            if (lane == 0) g_cand[blockIdx.x * KW + r] = m;
            if (k0 == m) k0 = 0ull;
            if (k1 == m) k1 = 0ull;
        }
    }

    // last-done block merges (detection only — no spinning)
    if (tid == 0) {
        __threadfence();                         // publish g_cand
        unsigned old = atomicAdd(&g_done, 1);
        s_last = (((old + 1) % (unsigned)nblocks) == 0u) ? 1u : 0u;
    }
    __syncthreads();
    if (!s_last) return;
    __threadfence();                             // acquire candidate writes

    const int ncand = nblocks * KW;              // 625 for vocab=128000
    unsigned long long k[5];
    #pragma unroll
    for (int j = 0; j < 5; j++) {
        int i = tid + j * NT;
        k[j] = (i < ncand) ? __ldcg(&g_cand[i]) : 0ull;
    }

    __syncthreads();                             // sw reuse
    #pragma unroll
    for (int r = 0; r < KW; r++) {
        unsigned long long m = k[0];
        #pragma unroll
        for (int j = 1; j < 5; j++) if (k[j] > m) m = k[j];
        m = warp_max(m);
        if (lane == 0) sw[wid * KW + r] = m;
        #pragma unroll
        for (int j = 0; j < 5; j++) if (k[j] == m) k[j] = 0ull;
    }
    __syncthreads();

    if (wid == 0) {
        unsigned long long a0 = sw[lane];
        unsigned long long a1 = (lane < NW * KW - 32) ? sw[32 + lane] : 0ull;
        #pragma unroll
        for (int r = 0; r < KW; r++) {
            unsigned long long m = (a0 > a1) ? a0 : a1;
            m = warp_max(m);
            if (lane == 0 && m != 0ull) {
                unsigned idx = 0xFFFFFFFFu - (unsigned)(m & 0xFFFFFFFFull);
                out[idx] = GAIN_UP;
            }
            if (a0 == m) a0 = 0ull;
            if (a1 == m) a1 = 0ull;
        }
    }
}

// ---------------------------------------------------------------- launch
extern "C" void kernel_launch(void* const* d_in, const int* in_sizes, int n_in,
                              void* d_out, int out_size) {
    const int*   tok = (const int*)d_in[0];
    const float* v0  = (const float*)d_in[1];
    const int seq   = in_sizes[0];
    const int vocab = in_sizes[1];
    float* out = (float*)d_out;

    k_hist<<<(seq + NT - 1) / NT, NT>>>(tok, seq, vocab);

    int gblocks = (vocab + 4 * NT - 1) / (4 * NT);   // 125 for vocab=128000
    if (gblocks > MAXB) gblocks = MAXB;               // never hit at this size
    k_gains<<<gblocks, NT>>>(v0, out, vocab, gblocks);
}